// round 4
// baseline (speedup 1.0000x reference)
#include <cuda_runtime.h>
#include <math.h>

#define NQ 14
#define NSTATE (1 << NQ)
#define NT 512
#define PI_F 3.14159265358979323846f

typedef unsigned long long u64;

// ---------------------------------------------------------------------------
// packed f32x2 helpers
// ---------------------------------------------------------------------------
__device__ __forceinline__ u64 pk(float a, float b) {
    u64 r; asm("mov.b64 %0,{%1,%2};" : "=l"(r) : "f"(a), "f"(b)); return r;
}
__device__ __forceinline__ void unpk(u64 v, float& a, float& b) {
    asm("mov.b64 {%0,%1},%2;" : "=f"(a), "=f"(b) : "l"(v));
}
__device__ __forceinline__ u64 fma2(u64 a, u64 b, u64 c) {
    u64 d; asm("fma.rn.f32x2 %0,%1,%2,%3;" : "=l"(d) : "l"(a), "l"(b), "l"(c)); return d;
}
__device__ __forceinline__ u64 mul2(u64 a, u64 b) {
    u64 d; asm("mul.rn.f32x2 %0,%1,%2;" : "=l"(d) : "l"(a), "l"(b)); return d;
}
__device__ __forceinline__ u64 add2(u64 a, u64 b) {
    u64 d; asm("add.rn.f32x2 %0,%1,%2;" : "=l"(d) : "l"(a), "l"(b)); return d;
}

__device__ __forceinline__ float2 cmul(float2 a, float2 b) {
    float2 r;
    r.x = a.x * b.x - a.y * b.y;
    r.y = a.x * b.y + a.y * b.x;
    return r;
}

// swizzle: slot bits1-4 ^= bits5-8; bit0 = index bit0 only (64-bit pairing)
__host__ __device__ constexpr int slotf(int a) {
    return a ^ (((a >> 5) & 15) << 1);
}
// suffix-xor (inverse of y -> y^(y>>1)), XOR-linear
__host__ __device__ constexpr int sxf(int a) {
    a ^= a >> 1; a ^= a >> 2; a ^= a >> 4; a ^= a >> 8;
    return a;
}
__host__ __device__ constexpr int parc(int a) {
    a ^= a >> 8; a ^= a >> 4; a ^= a >> 2; a ^= a >> 1;
    return a & 1;
}

// shared tables
__shared__ float2 gT[3][NQ][12];  // splat coeffs; [13] = 6-entry reg-gate layout
__shared__ float2 v0[NQ][2];      // per-qubit vector after encoding + layer0
__shared__ float  red[16][16];

__device__ __forceinline__ u64 ld8(const float2* p) {
    return *reinterpret_cast<const u64*>(p);
}

// U = RZ(rz) @ RY(ry) @ RX(rx)
__device__ __forceinline__ void make_u(float rx, float ry, float rz, float2 U[4]) {
    float cx, sx, cy, sy, cz, sz;
    sincosf(0.5f * rx, &sx, &cx);
    sincosf(0.5f * ry, &sy, &cy);
    sincosf(0.5f * rz, &sz, &cz);
    float2 M00 = { cy * cx,  sy * sx };
    float2 M01 = {-sy * cx, -cy * sx };
    float2 M10 = { sy * cx, -cy * sx };
    float2 M11 = { cy * cx, -sy * sx };
    float2 p = { cz, -sz };
    float2 q = { cz,  sz };
    U[0] = cmul(p, M00);
    U[1] = cmul(p, M01);
    U[2] = cmul(q, M10);
    U[3] = cmul(q, M11);
}

__device__ __forceinline__ void bfly(u64& a0r, u64& a0i, u64& a1r, u64& a1i,
                                     u64 X00, u64 Y00, u64 M00,
                                     u64 X01, u64 Y01, u64 M01,
                                     u64 X10, u64 Y10, u64 M10,
                                     u64 X11, u64 Y11, u64 M11) {
    u64 n0r = fma2(M01, a1i, fma2(X01, a1r, fma2(M00, a0i, mul2(X00, a0r))));
    u64 n0i = fma2(X01, a1i, fma2(Y01, a1r, fma2(X00, a0i, mul2(Y00, a0r))));
    u64 n1r = fma2(M11, a1i, fma2(X11, a1r, fma2(M10, a0i, mul2(X10, a0r))));
    u64 n1i = fma2(X11, a1i, fma2(Y11, a1r, fma2(X10, a0i, mul2(Y10, a0r))));
    a0r = n0r; a0i = n0i; a1r = n1r; a1i = n1i;
}

// 4 jj-bit gates at index positions P0..P3 (qubit = 13 - pos)
template<int P0, int P1, int P2, int P3>
__device__ __forceinline__ void gates4(u64* cr, u64* ci, const float2 (*g)[12]) {
#pragma unroll
    for (int k = 0; k < 4; k++) {
        const int pos = (k == 0) ? P0 : (k == 1) ? P1 : (k == 2) ? P2 : P3;
        const int q = 13 - pos;
        const u64 X00 = ld8(&g[q][0]),  Y00 = ld8(&g[q][1]),  M00 = ld8(&g[q][2]);
        const u64 X01 = ld8(&g[q][3]),  Y01 = ld8(&g[q][4]),  M01 = ld8(&g[q][5]);
        const u64 X10 = ld8(&g[q][6]),  Y10 = ld8(&g[q][7]),  M10 = ld8(&g[q][8]);
        const u64 X11 = ld8(&g[q][9]),  Y11 = ld8(&g[q][10]), M11 = ld8(&g[q][11]);
#pragma unroll
        for (int jj = 0; jj < 16; jj++) {
            if (jj & (1 << k)) continue;
            const int j2 = jj | (1 << k);
            bfly(cr[jj], ci[jj], cr[j2], ci[j2],
                 X00, Y00, M00, X01, Y01, M01, X10, Y10, M10, X11, Y11, M11);
        }
    }
}

// in-register gate on pack bit (qubit 13); g[13] 6-entry layout
__device__ __forceinline__ void reggate13(u64* cr, u64* ci, const float2 (*g)[12]) {
    const u64 A  = ld8(&g[13][0]), B  = ld8(&g[13][1]);
    const u64 E  = ld8(&g[13][2]), F  = ld8(&g[13][3]);
    const u64 Cm = ld8(&g[13][4]), Dm = ld8(&g[13][5]);
#pragma unroll
    for (int jj = 0; jj < 16; jj++) {
        float r0, r1, i0, i1;
        unpk(cr[jj], r0, r1);
        unpk(ci[jj], i0, i1);
        const u64 sar = pk(r1, r0), sai = pk(i1, i0);
        const u64 nr = fma2(Dm, sai, fma2(Cm, ci[jj], fma2(B, sar, mul2(A, cr[jj]))));
        const u64 ni = fma2(B,  sai, fma2(A,  ci[jj], fma2(F, sar, mul2(E, cr[jj]))));
        cr[jj] = nr; ci[jj] = ni;
    }
}

// shfl gate on qubit 8 (index bit 5 = lane bit 4 in RT1 layout)
__device__ __forceinline__ void shflgate8(u64* cr, u64* ci, const float2 (*g)[12],
                                          int lane) {
    const bool odd = (lane >> 4) & 1;
    const u64 Gr = odd ? ld8(&g[8][9])  : ld8(&g[8][0]);
    const u64 Gi = odd ? ld8(&g[8][10]) : ld8(&g[8][1]);
    const u64 Gm = odd ? ld8(&g[8][11]) : ld8(&g[8][2]);
    const u64 Hr = odd ? ld8(&g[8][6])  : ld8(&g[8][3]);
    const u64 Hi = odd ? ld8(&g[8][7])  : ld8(&g[8][4]);
    const u64 Hm = odd ? ld8(&g[8][8])  : ld8(&g[8][5]);
#pragma unroll
    for (int jj = 0; jj < 16; jj++) {
        const u64 pr = __shfl_xor_sync(0xFFFFFFFFu, cr[jj], 16);
        const u64 pi = __shfl_xor_sync(0xFFFFFFFFu, ci[jj], 16);
        const u64 nr = fma2(Hm, pi, fma2(Hr, pr, fma2(Gm, ci[jj], mul2(Gr, cr[jj]))));
        const u64 ni = fma2(Hr, pi, fma2(Hi, pr, fma2(Gr, ci[jj], mul2(Gi, cr[jj]))));
        cr[jj] = nr; ci[jj] = ni;
    }
}

// RT1 K-slot: K = jj<<6  => slotf = (jj<<6) ^ ((jj&7)<<2)
__device__ __forceinline__ constexpr int kslot1(int jj) {
    return (jj << 6) ^ ((jj & 7) << 2);
}

// ---------------------------------------------------------------------------
__global__ void __launch_bounds__(NT, 1)
qc_kernel(const float* __restrict__ x,
          const float* __restrict__ prx,
          const float* __restrict__ pry,
          const float* __restrict__ prz,
          const float* __restrict__ pent,
          float* __restrict__ out) {
    extern __shared__ float smem[];
    float* sre = smem;            // 16384 floats
    float* sim = smem + NSTATE;   // 16384 floats

    const int b    = blockIdx.x;
    const int tid  = threadIdx.x;
    const int lane = tid & 31;
    const int warp = tid >> 5;

    // ---- setup: coefficient tables, layers 1..3 (ent phases merged) --------
    if (tid < 42) {
        const int t = tid / NQ;
        const int i = tid % NQ;
        const int l = t + 1;
        float2 U[4];
        make_u(prx[l * NQ + i], pry[l * NQ + i], prz[l * NQ + i], U);
        if (i > 0) {
            float ce, se;
            sincosf(0.5f * pent[t * (NQ - 1) + (i - 1)], &se, &ce);
            float2 pe = { ce, -se };
            float2 qe = { ce,  se };
            U[0] = cmul(U[0], pe);
            U[2] = cmul(U[2], pe);
            U[1] = cmul(U[1], qe);
            U[3] = cmul(U[3], qe);
        }
        if (i == 13) {
            gT[t][i][0] = make_float2( U[0].x,  U[3].x);
            gT[t][i][1] = make_float2( U[1].x,  U[2].x);
            gT[t][i][2] = make_float2( U[0].y,  U[3].y);
            gT[t][i][3] = make_float2( U[1].y,  U[2].y);
            gT[t][i][4] = make_float2(-U[0].y, -U[3].y);
            gT[t][i][5] = make_float2(-U[1].y, -U[2].y);
        } else {
#pragma unroll
            for (int r = 0; r < 4; r++) {
                gT[t][i][r * 3 + 0] = make_float2( U[r].x,  U[r].x);
                gT[t][i][r * 3 + 1] = make_float2( U[r].y,  U[r].y);
                gT[t][i][r * 3 + 2] = make_float2(-U[r].y, -U[r].y);
            }
        }
    }
    if (tid >= 64 && tid < 64 + NQ) {
        const int i = tid - 64;
        float2 U[4];
        make_u(prx[i], pry[i], prz[i], U);
        const float enc = tanhf(x[b * NQ + i]) * PI_F;
        float ce, se;
        sincosf(0.5f * enc, &se, &ce);
        float2 a, c2;
        a.x  = U[0].x * ce + U[1].x * se;
        a.y  = U[0].y * ce + U[1].y * se;
        c2.x = U[2].x * ce + U[3].x * se;
        c2.y = U[2].y * ce + U[3].y * se;
        v0[i][0] = a;
        v0[i][1] = c2;
    }
    __syncthreads();

    // slot bases for the three register-tile layouts
    // RT1: lane->bits1-5, warp->bits10-13, jj->bits6-9, pack->bit0
    // RT2: lane->bits5-9, warp->bits10-13, jj->bits1-4, pack->bit0
    // RT3: lane->bits1-5, warp->bits6-9,  jj->bits10-13, pack->bit0
    const int sb1 = ((lane << 1) | (warp << 10)) ^ (((lane >> 4) & 1) << 1);
    const int sb2 = ((lane << 5) | (warp << 10)) ^ ((lane & 15) << 1);
    const int base3 = (lane << 1) | (warp << 6);
    const int sb3 = base3 ^ (((((lane >> 4) & 1) | ((warp & 7) << 1))) << 1);

    u64 cr[16], ci[16];

#pragma unroll 1
    for (int t = 0; t < 3; t++) {
        const float2 (*g)[12] = gT[t];

        // ---- RT1: gates q13(reg), q7,q6,q5,q4(jj), q8(shfl) ---------------
        if (t == 0) {
            // init directly into RT1 registers: amp[z] = prod v0[13-p][gray(z)_p]
            const int l = lane, w = warp;
            float2 F = v0[12][(l ^ (l >> 1)) & 1];
            F = cmul(F, v0[11][((l >> 1) ^ (l >> 2)) & 1]);
            F = cmul(F, v0[10][((l >> 2) ^ (l >> 3)) & 1]);
            F = cmul(F, v0[ 9][((l >> 3) ^ (l >> 4)) & 1]);
            F = cmul(F, v0[ 3][( w       ^ (w >> 1)) & 1]);
            F = cmul(F, v0[ 2][((w >> 1) ^ (w >> 2)) & 1]);
            F = cmul(F, v0[ 1][((w >> 2) ^ (w >> 3)) & 1]);
            F = cmul(F, v0[ 0][ (w >> 3)             & 1]);
            const int l0 = l & 1, l4 = (l >> 4) & 1, w0 = w & 1;
            const float2 e0 = v0[13][l0], e1 = v0[13][l0 ^ 1];
#pragma unroll
            for (int jj = 0; jj < 16; jj++) {
                float2 H = cmul(F, v0[8][(l4 ^ jj) & 1]);
                H = cmul(H, v0[7][( jj       ^ (jj >> 1)) & 1]);
                H = cmul(H, v0[6][((jj >> 1) ^ (jj >> 2)) & 1]);
                H = cmul(H, v0[5][((jj >> 2) ^ (jj >> 3)) & 1]);
                H = cmul(H, v0[4][((jj >> 3) ^ w0) & 1]);
                const float2 alo = cmul(H, e0);
                const float2 ahi = cmul(H, e1);
                cr[jj] = pk(alo.x, ahi.x);
                ci[jj] = pk(alo.y, ahi.y);
            }
        } else {
#pragma unroll
            for (int jj = 0; jj < 16; jj++) {
                const int a = sb1 ^ kslot1(jj);
                cr[jj] = *reinterpret_cast<const u64*>(&sre[a]);
                ci[jj] = *reinterpret_cast<const u64*>(&sim[a]);
            }
        }
        reggate13(cr, ci, g);
        gates4<6, 7, 8, 9>(cr, ci, g);
        shflgate8(cr, ci, g, lane);
#pragma unroll
        for (int jj = 0; jj < 16; jj++) {
            const int a = sb1 ^ kslot1(jj);
            *reinterpret_cast<u64*>(&sre[a]) = cr[jj];
            *reinterpret_cast<u64*>(&sim[a]) = ci[jj];
        }
        __syncwarp();   // RT1->RT2 exchange is warp-local (same warp bits)

        // ---- RT2: gates q12,q11,q10,q9 ------------------------------------
#pragma unroll
        for (int jj = 0; jj < 16; jj++) {
            const int a = sb2 ^ (jj << 1);
            cr[jj] = *reinterpret_cast<const u64*>(&sre[a]);
            ci[jj] = *reinterpret_cast<const u64*>(&sim[a]);
        }
        gates4<1, 2, 3, 4>(cr, ci, g);
#pragma unroll
        for (int jj = 0; jj < 16; jj++) {
            const int a = sb2 ^ (jj << 1);
            *reinterpret_cast<u64*>(&sre[a]) = cr[jj];
            *reinterpret_cast<u64*>(&sim[a]) = ci[jj];
        }
        __syncthreads();

        if (t == 2) break;

        // ---- RT3: gates q3,q2,q1,q0 + entangle perm store ------------------
#pragma unroll
        for (int jj = 0; jj < 16; jj++) {
            const int a = sb3 ^ (jj << 10);
            cr[jj] = *reinterpret_cast<const u64*>(&sre[a]);
            ci[jj] = *reinterpret_cast<const u64*>(&sim[a]);
        }
        gates4<10, 11, 12, 13>(cr, ci, g);
        __syncthreads();  // in-place permuted store: all loads complete first
        {
            const int sxb = slotf(sxf(base3));
            const int pb  = __popc(base3) & 1;
#pragma unroll
            for (int jj = 0; jj < 16; jj++) {
                const int K = jj << 10;
                const int tadr = (sxb ^ slotf(sxf(K))) & ~1;
                const bool swap = (pb ^ parc(K)) != 0;
                u64 vr = cr[jj], vi = ci[jj];
                if (swap) {
                    float a2, b2;
                    unpk(vr, a2, b2); vr = pk(b2, a2);
                    unpk(vi, a2, b2); vi = pk(b2, a2);
                }
                *reinterpret_cast<u64*>(&sre[tadr]) = vr;
                *reinterpret_cast<u64*>(&sim[tadr]) = vi;
            }
        }
        __syncthreads();
    }

    // ---- final RT3 (layer 3): gates q3..q0, then measure from registers ----
    {
        const float2 (*g)[12] = gT[2];
#pragma unroll
        for (int jj = 0; jj < 16; jj++) {
            const int a = sb3 ^ (jj << 10);
            cr[jj] = *reinterpret_cast<const u64*>(&sre[a]);
            ci[jj] = *reinterpret_cast<const u64*>(&sim[a]);
        }
        gates4<10, 11, 12, 13>(cr, ci, g);
    }

    // measurement with final entangle perm applied arithmetically: y = sxf(z)
    u64 tE = 0, tO = 0, q0a = 0, q1a = 0, q2a = 0, q3a = 0;
#pragma unroll
    for (int jj = 0; jj < 16; jj++) {
        const u64 p2 = fma2(ci[jj], ci[jj], mul2(cr[jj], cr[jj]));
        const int par1 = __popc(jj) & 1;          // y10 (qubit 3), K-parity
        const int par2 = __popc(jj >> 1) & 1;     // y11 (qubit 2)
        const int par3 = __popc(jj >> 2) & 1;     // y12 (qubit 1)
        const int par4 = (jj >> 3) & 1;           // y13 (qubit 0)
        if (par1) { tO = add2(tO, p2); q3a = add2(q3a, p2); }
        else      { tE = add2(tE, p2); }
        if (par2) q2a = add2(q2a, p2);
        if (par3) q1a = add2(q1a, p2);
        if (par4) q0a = add2(q0a, p2);
    }

    float s[NQ], tsum;
    {
        float tEl, tEh, tOl, tOh;
        unpk(tE, tEl, tEh);
        unpk(tO, tOl, tOh);
        const float tE2 = tEl + tEh, tO2 = tOl + tOh;
        tsum = tE2 + tO2;
        float a2, b2;
        unpk(q0a, a2, b2); s[0] = a2 + b2;
        unpk(q1a, a2, b2); s[1] = a2 + b2;
        unpk(q2a, a2, b2); s[2] = a2 + b2;
        unpk(q3a, a2, b2); s[3] = a2 + b2;
        const int pb = __popc(base3) & 1;
        s[13] = pb ? (tEl + tOh) : (tEh + tOl);
#pragma unroll
        for (int q = 4; q < 13; q++) {
            const int p = 13 - q;  // y bit 9..1
            const int bE = __popc(base3 >> p) & 1;
            s[q] = bE ? tE2 : tO2;
        }
    }

#pragma unroll
    for (int o = 16; o; o >>= 1) {
        tsum += __shfl_xor_sync(0xFFFFFFFFu, tsum, o);
#pragma unroll
        for (int q = 0; q < NQ; q++)
            s[q] += __shfl_xor_sync(0xFFFFFFFFu, s[q], o);
    }
    if (lane == 0) {
        red[warp][0] = tsum;
#pragma unroll
        for (int q = 0; q < NQ; q++) red[warp][1 + q] = s[q];
    }
    __syncthreads();

    if (tid < NQ) {
        float tt = 0.f, ss = 0.f;
#pragma unroll
        for (int w = 0; w < 16; w++) {
            tt += red[w][0];
            ss += red[w][1 + tid];
        }
        out[b * NQ + tid] = tt - 2.f * ss;
    }
}

// ---------------------------------------------------------------------------
extern "C" void kernel_launch(void* const* d_in, const int* in_sizes, int n_in,
                              void* d_out, int out_size) {
    const float* x    = (const float*)d_in[0];
    const float* prx  = (const float*)d_in[1];
    const float* pry  = (const float*)d_in[2];
    const float* prz  = (const float*)d_in[3];
    const float* pent = (const float*)d_in[4];
    float* out = (float*)d_out;

    const int B = in_sizes[0] / NQ;
    const size_t smem = 2 * NSTATE * sizeof(float);  // 131072 bytes SoA

    cudaFuncSetAttribute(qc_kernel,
                         cudaFuncAttributeMaxDynamicSharedMemorySize,
                         (int)smem);
    qc_kernel<<<B, NT, smem>>>(x, prx, pry, prz, pent, out);
}